// round 2
// baseline (speedup 1.0000x reference)
#include <cuda_runtime.h>

#define DV 128
#define HH 256
#define WW 256
#define BB 2
#define NSTEPS 111
#define DT 0.03125f
#define DDD (DV*DV*DV)

// Static device scratch: volume permuted to AoS float4 (r,g,b,sigma) per voxel.
// 2 * 128^3 * 16B = 64 MB.
__device__ float4 g_vol[BB * DDD];

__global__ void permute_kernel(const float* __restrict__ vol) {
    int i = blockIdx.x * blockDim.x + threadIdx.x;
    if (i >= BB * DDD) return;
    int b = i / DDD;
    int v = i - b * DDD;
    const float* p = vol + (size_t)b * 4 * DDD + v;
    g_vol[i] = make_float4(p[0], p[DDD], p[2 * DDD], p[3 * DDD]);
}

__device__ __forceinline__ float4 lerp4(float4 a, float4 b, float f) {
    float omf = 1.0f - f;
    return make_float4(a.x * omf + b.x * f,
                       a.y * omf + b.y * f,
                       a.z * omf + b.z * f,
                       a.w * omf + b.w * f);
}

__global__ __launch_bounds__(256)
void raymarch_kernel(const float* __restrict__ camrot,
                     const float* __restrict__ campos,
                     const float* __restrict__ focal,
                     const float* __restrict__ princpt,
                     const float* __restrict__ pixelcoords,
                     float* __restrict__ out) {
    int x = blockIdx.x * blockDim.x + threadIdx.x;
    int y = blockIdx.y * blockDim.y + threadIdx.y;
    int b = blockIdx.z;
    if (x >= WW || y >= HH) return;

    // ---- ray setup (bit-exact IEEE ops: no fma contraction, real div/sqrt) ----
    const float* pc = pixelcoords + (((size_t)b * HH + y) * WW + x) * 2;
    float vx = __fdiv_rn(__fsub_rn(pc[0], princpt[b * 2 + 0]), focal[b * 2 + 0]);
    float vy = __fdiv_rn(__fsub_rn(pc[1], princpt[b * 2 + 1]), focal[b * 2 + 1]);

    // world_j = sum_i R[i][j] * v_i   (identity here -> exact passthrough)
    const float* R = camrot + b * 9;
    float dx = __fadd_rn(__fadd_rn(__fmul_rn(R[0], vx), __fmul_rn(R[3], vy)), R[6]);
    float dy = __fadd_rn(__fadd_rn(__fmul_rn(R[1], vx), __fmul_rn(R[4], vy)), R[7]);
    float dz = __fadd_rn(__fadd_rn(__fmul_rn(R[2], vx), __fmul_rn(R[5], vy)), R[8]);

    float n2 = __fadd_rn(__fadd_rn(__fmul_rn(dx, dx), __fmul_rn(dy, dy)),
                         __fmul_rn(dz, dz));
    float nr = __fsqrt_rn(n2);
    dx = __fdiv_rn(dx, nr);
    dy = __fdiv_rn(dy, nr);
    dz = __fdiv_rn(dz, nr);

    float cx = campos[b * 3 + 0];
    float cy = campos[b * 3 + 1];
    float cz = campos[b * 3 + 2];

    // ---- ray-AABB intersection with [-1,1]^3 (exact divides; inf on /0) ----
    float t1x = __fdiv_rn(__fsub_rn(-1.0f, cx), dx);
    float t2x = __fdiv_rn(__fsub_rn( 1.0f, cx), dx);
    float t1y = __fdiv_rn(__fsub_rn(-1.0f, cy), dy);
    float t2y = __fdiv_rn(__fsub_rn( 1.0f, cy), dy);
    float t1z = __fdiv_rn(__fsub_rn(-1.0f, cz), dz);
    float t2z = __fdiv_rn(__fsub_rn( 1.0f, cz), dz);
    float tmin = fmaxf(fminf(t1x, t2x), fmaxf(fminf(t1y, t2y), fminf(t1z, t2z)));
    float tmax = fminf(fmaxf(t1x, t2x), fminf(fmaxf(t1y, t2y), fmaxf(t1z, t2z)));

    float r = 0.0f, g = 0.0f, bl = 0.0f, alpha = 0.0f;
    size_t obase = ((size_t)b * 4) * HH * WW + (size_t)y * WW + x;

    bool hit = tmin < tmax;
    if (hit && tmax > 0.0f) {
        float t0 = fmaxf(tmin, 0.0f);
        // raypos0 = campos + raydir * t0, no contraction (matches XLA mul+add)
        float px = __fadd_rn(cx, __fmul_rn(dx, t0));
        float py = __fadd_rn(cy, __fmul_rn(dy, t0));
        float pz = __fadd_rn(cz, __fmul_rn(dz, t0));
        // DT = 2^-5 exactly -> d*DT exact, step adds bit-identical to reference
        float sx = __fmul_rn(dx, DT);
        float sy = __fmul_rn(dy, DT);
        float sz = __fmul_rn(dz, DT);

        const float4* __restrict__ vb = g_vol + (size_t)b * DDD;
        bool entered = false;

        #pragma unroll 1
        for (int s = 0; s < NSTEPS; ++s) {
            bool valid = (px > -1.0f) & (px < 1.0f) &
                         (py > -1.0f) & (py < 1.0f) &
                         (pz > -1.0f) & (pz < 1.0f);
            if (valid) {
                entered = true;
                // grid coords, align_corners=True, n=128 (continuous path;
                // rounding here cannot flip discrete decisions)
                float gx = fminf(fmaxf((px + 1.0f) * 0.5f * 127.0f, 0.0f), 127.0f);
                float gy = fminf(fmaxf((py + 1.0f) * 0.5f * 127.0f, 0.0f), 127.0f);
                float gz = fminf(fmaxf((pz + 1.0f) * 0.5f * 127.0f, 0.0f), 127.0f);
                int ix = min((int)gx, DV - 2);
                int iy = min((int)gy, DV - 2);
                int iz = min((int)gz, DV - 2);
                float fx = gx - (float)ix;
                float fy = gy - (float)iy;
                float fz = gz - (float)iz;

                int idx = (iz * DV + iy) * DV + ix;
                float4 c000 = __ldg(vb + idx);
                float4 c001 = __ldg(vb + idx + 1);
                float4 c010 = __ldg(vb + idx + DV);
                float4 c011 = __ldg(vb + idx + DV + 1);
                float4 c100 = __ldg(vb + idx + DV * DV);
                float4 c101 = __ldg(vb + idx + DV * DV + 1);
                float4 c110 = __ldg(vb + idx + DV * DV + DV);
                float4 c111 = __ldg(vb + idx + DV * DV + DV + 1);

                float4 c00 = lerp4(c000, c001, fx);
                float4 c01 = lerp4(c010, c011, fx);
                float4 c10 = lerp4(c100, c101, fx);
                float4 c11 = lerp4(c110, c111, fx);
                float4 c0 = lerp4(c00, c01, fy);
                float4 c1 = lerp4(c10, c11, fy);
                float4 smp = lerp4(c0, c1, fz);

                // contrib = min(alpha + sigma*DT, 1) - alpha   (sigma*DT exact: DT=2^-5)
                float contrib = __fsub_rn(fminf(__fadd_rn(alpha, __fmul_rn(smp.w, DT)), 1.0f),
                                          alpha);
                r  = __fadd_rn(r,  __fmul_rn(smp.x, contrib));
                g  = __fadd_rn(g,  __fmul_rn(smp.y, contrib));
                bl = __fadd_rn(bl, __fmul_rn(smp.z, contrib));
                alpha = __fadd_rn(alpha, contrib);
                if (alpha >= 1.0f) break;   // contrib exactly 0 from here on
            } else if (entered) {
                break;                       // convex box + monotone coords: left for good
            }
            px = __fadd_rn(px, sx);
            py = __fadd_rn(py, sy);
            pz = __fadd_rn(pz, sz);
        }
    }

    out[obase]               = r;
    out[obase + HH * WW]     = g;
    out[obase + 2 * HH * WW] = bl;
    out[obase + 3 * HH * WW] = alpha;
}

extern "C" void kernel_launch(void* const* d_in, const int* in_sizes, int n_in,
                              void* d_out, int out_size) {
    const float* camrot      = (const float*)d_in[0];
    const float* campos      = (const float*)d_in[1];
    const float* focal       = (const float*)d_in[2];
    const float* princpt     = (const float*)d_in[3];
    const float* pixelcoords = (const float*)d_in[4];
    const float* volume      = (const float*)d_in[5];
    float* out = (float*)d_out;

    int nvox = BB * DDD;
    permute_kernel<<<(nvox + 255) / 256, 256>>>(volume);

    dim3 block(32, 8, 1);
    dim3 grid(WW / 32, HH / 8, BB);
    raymarch_kernel<<<grid, block>>>(camrot, campos, focal, princpt,
                                     pixelcoords, out);
}

// round 3
// speedup vs baseline: 1.2573x; 1.2573x over previous
#include <cuda_runtime.h>

#define DV 128
#define HH 256
#define WW 256
#define BB 2
#define NSTEPS 111
#define DT 0.03125f
#define DDD (DV*DV*DV)

// Static device scratch: volume permuted to AoS float4 (r,g,b,sigma) per voxel.
// 2 * 128^3 * 16B = 64 MB.
__device__ float4 g_vol[BB * DDD];

__global__ void permute_kernel(const float* __restrict__ vol) {
    int i = blockIdx.x * blockDim.x + threadIdx.x;
    if (i >= BB * DDD) return;
    int b = i / DDD;
    int v = i - b * DDD;
    const float* p = vol + (size_t)b * 4 * DDD + v;
    g_vol[i] = make_float4(p[0], p[DDD], p[2 * DDD], p[3 * DDD]);
}

__device__ __forceinline__ float4 lerp4(float4 a, float4 b, float f) {
    float omf = 1.0f - f;
    return make_float4(a.x * omf + b.x * f,
                       a.y * omf + b.y * f,
                       a.z * omf + b.z * f,
                       a.w * omf + b.w * f);
}

// blockDim = (64, 4): lane pair (2k, 2k+1) processes one ray; parity = z-plane.
__global__ __launch_bounds__(256)
void raymarch_kernel(const float* __restrict__ camrot,
                     const float* __restrict__ campos,
                     const float* __restrict__ focal,
                     const float* __restrict__ princpt,
                     const float* __restrict__ pixelcoords,
                     float* __restrict__ out) {
    int p = threadIdx.x & 1;                                // 0: z0-plane, 1: z1-plane
    int x = blockIdx.x * 32 + (threadIdx.x >> 1);
    int y = blockIdx.y * blockDim.y + threadIdx.y;
    int b = blockIdx.z;

    // ---- ray setup (bit-exact IEEE ops: no fma contraction, real div/sqrt) ----
    const float* pc = pixelcoords + (((size_t)b * HH + y) * WW + x) * 2;
    float vx = __fdiv_rn(__fsub_rn(pc[0], princpt[b * 2 + 0]), focal[b * 2 + 0]);
    float vy = __fdiv_rn(__fsub_rn(pc[1], princpt[b * 2 + 1]), focal[b * 2 + 1]);

    const float* R = camrot + b * 9;   // world_j = sum_i R[i][j] * v_i
    float dx = __fadd_rn(__fadd_rn(__fmul_rn(R[0], vx), __fmul_rn(R[3], vy)), R[6]);
    float dy = __fadd_rn(__fadd_rn(__fmul_rn(R[1], vx), __fmul_rn(R[4], vy)), R[7]);
    float dz = __fadd_rn(__fadd_rn(__fmul_rn(R[2], vx), __fmul_rn(R[5], vy)), R[8]);

    float n2 = __fadd_rn(__fadd_rn(__fmul_rn(dx, dx), __fmul_rn(dy, dy)),
                         __fmul_rn(dz, dz));
    float nr = __fsqrt_rn(n2);
    dx = __fdiv_rn(dx, nr);
    dy = __fdiv_rn(dy, nr);
    dz = __fdiv_rn(dz, nr);

    float cx = campos[b * 3 + 0];
    float cy = campos[b * 3 + 1];
    float cz = campos[b * 3 + 2];

    // ---- ray-AABB intersection with [-1,1]^3 (exact divides; inf on /0) ----
    float t1x = __fdiv_rn(__fsub_rn(-1.0f, cx), dx);
    float t2x = __fdiv_rn(__fsub_rn( 1.0f, cx), dx);
    float t1y = __fdiv_rn(__fsub_rn(-1.0f, cy), dy);
    float t2y = __fdiv_rn(__fsub_rn( 1.0f, cy), dy);
    float t1z = __fdiv_rn(__fsub_rn(-1.0f, cz), dz);
    float t2z = __fdiv_rn(__fsub_rn( 1.0f, cz), dz);
    float tmin = fmaxf(fminf(t1x, t2x), fmaxf(fminf(t1y, t2y), fminf(t1z, t2z)));
    float tmax = fminf(fmaxf(t1x, t2x), fminf(fmaxf(t1y, t2y), fmaxf(t1z, t2z)));

    float r = 0.0f, g = 0.0f, bl = 0.0f, alpha = 0.0f;
    size_t obase = ((size_t)b * 4) * HH * WW + (size_t)y * WW + x;

    bool hit = tmin < tmax;
    if (hit && tmax > 0.0f) {
        float t0 = fmaxf(tmin, 0.0f);
        float px = __fadd_rn(cx, __fmul_rn(dx, t0));
        float py = __fadd_rn(cy, __fmul_rn(dy, t0));
        float pz = __fadd_rn(cz, __fmul_rn(dz, t0));
        // DT = 2^-5 exactly -> d*DT exact, step adds bit-identical to reference
        float sx = __fmul_rn(dx, DT);
        float sy = __fmul_rn(dy, DT);
        float sz = __fmul_rn(dz, DT);

        const float4* __restrict__ vb = g_vol + (size_t)b * DDD + p * (DV * DV);
        bool entered = false;

        #pragma unroll 1
        for (int s = 0; s < NSTEPS; ++s) {
            bool valid = (px > -1.0f) & (px < 1.0f) &
                         (py > -1.0f) & (py < 1.0f) &
                         (pz > -1.0f) & (pz < 1.0f);
            if (valid) {
                entered = true;
                float gx = fminf(fmaxf((px + 1.0f) * 0.5f * 127.0f, 0.0f), 127.0f);
                float gy = fminf(fmaxf((py + 1.0f) * 0.5f * 127.0f, 0.0f), 127.0f);
                float gz = fminf(fmaxf((pz + 1.0f) * 0.5f * 127.0f, 0.0f), 127.0f);
                int ix = min((int)gx, DV - 2);
                int iy = min((int)gy, DV - 2);
                int iz = min((int)gz, DV - 2);
                float fx = gx - (float)ix;
                float fy = gy - (float)iy;
                float fz = gz - (float)iz;

                // this lane loads the 4 corners of its z-plane (iz + p)
                int idx = (iz * DV + iy) * DV + ix;
                float4 c00 = __ldg(vb + idx);
                float4 c01 = __ldg(vb + idx + 1);
                float4 c10 = __ldg(vb + idx + DV);
                float4 c11 = __ldg(vb + idx + DV + 1);

                float4 a0 = lerp4(c00, c01, fx);
                float4 a1 = lerp4(c10, c11, fx);
                float4 cp = lerp4(a0, a1, fy);         // bilinear result of plane iz+p

                // exchange with the sibling lane (identical control flow ->
                // the pair is always co-active in activemask)
                unsigned m = __activemask();
                float4 cq;
                cq.x = __shfl_xor_sync(m, cp.x, 1);
                cq.y = __shfl_xor_sync(m, cp.y, 1);
                cq.z = __shfl_xor_sync(m, cp.z, 1);
                cq.w = __shfl_xor_sync(m, cp.w, 1);

                float4 c0 = (p == 0) ? cp : cq;        // z = iz plane
                float4 c1 = (p == 0) ? cq : cp;        // z = iz+1 plane
                float4 smp = lerp4(c0, c1, fz);

                // contrib = min(alpha + sigma*DT, 1) - alpha   (sigma*DT exact)
                float contrib = __fsub_rn(fminf(__fadd_rn(alpha, __fmul_rn(smp.w, DT)), 1.0f),
                                          alpha);
                r  = __fadd_rn(r,  __fmul_rn(smp.x, contrib));
                g  = __fadd_rn(g,  __fmul_rn(smp.y, contrib));
                bl = __fadd_rn(bl, __fmul_rn(smp.z, contrib));
                alpha = __fadd_rn(alpha, contrib);
                if (alpha >= 1.0f) break;   // contrib exactly 0 from here on
            } else if (entered) {
                break;                       // convex box: left for good
            }
            px = __fadd_rn(px, sx);
            py = __fadd_rn(py, sy);
            pz = __fadd_rn(pz, sz);
        }
    }

    if (p == 0) {
        out[obase]               = r;
        out[obase + HH * WW]     = g;
        out[obase + 2 * HH * WW] = bl;
        out[obase + 3 * HH * WW] = alpha;
    }
}

extern "C" void kernel_launch(void* const* d_in, const int* in_sizes, int n_in,
                              void* d_out, int out_size) {
    const float* camrot      = (const float*)d_in[0];
    const float* campos      = (const float*)d_in[1];
    const float* focal       = (const float*)d_in[2];
    const float* princpt     = (const float*)d_in[3];
    const float* pixelcoords = (const float*)d_in[4];
    const float* volume      = (const float*)d_in[5];
    float* out = (float*)d_out;

    int nvox = BB * DDD;
    permute_kernel<<<(nvox + 255) / 256, 256>>>(volume);

    dim3 block(64, 4, 1);                 // 256 threads = 128 rays (2 threads/ray)
    dim3 grid(WW / 32, HH / 4, BB);       // 8 x 64 x 2 = 1024 blocks
    raymarch_kernel<<<grid, block>>>(camrot, campos, focal, princpt,
                                     pixelcoords, out);
}

// round 5
// speedup vs baseline: 1.4790x; 1.1763x over previous
#include <cuda_runtime.h>
#include <cuda_fp16.h>

#define DV 128
#define HH 256
#define WW 256
#define BB 2
#define NSTEPS 111
#define DT 0.03125f
#define DDD (DV*DV*DV)

// Static device scratch: volume permuted to AoS half4 (r,g,b,sigma) per voxel,
// packed in a uint2 (8 bytes). 2 * 128^3 * 8B = 32 MB.
__device__ uint2 g_vol[BB * DDD];

__global__ void permute_kernel(const float* __restrict__ vol) {
    int i = blockIdx.x * blockDim.x + threadIdx.x;
    if (i >= BB * DDD) return;
    int b = i / DDD;
    int v = i - b * DDD;
    const float* p = vol + (size_t)b * 4 * DDD + v;
    __half2 lo = __floats2half2_rn(p[0], p[DDD]);
    __half2 hi = __floats2half2_rn(p[2 * DDD], p[3 * DDD]);
    uint2 out;
    out.x = *reinterpret_cast<unsigned*>(&lo);
    out.y = *reinterpret_cast<unsigned*>(&hi);
    g_vol[i] = out;
}

__device__ __forceinline__ float4 load4h(const uint2* __restrict__ vb, int idx) {
    uint2 raw = __ldg(vb + idx);
    __half2 lo = *reinterpret_cast<__half2*>(&raw.x);
    __half2 hi = *reinterpret_cast<__half2*>(&raw.y);
    float2 rg = __half22float2(lo);
    float2 ba = __half22float2(hi);
    return make_float4(rg.x, rg.y, ba.x, ba.y);
}

__device__ __forceinline__ float4 lerp4(float4 a, float4 b, float f) {
    float omf = 1.0f - f;
    return make_float4(a.x * omf + b.x * f,
                       a.y * omf + b.y * f,
                       a.z * omf + b.z * f,
                       a.w * omf + b.w * f);
}

// blockDim = (64, 4): lane pair (2k, 2k+1) processes one ray; parity = z-plane.
__global__ __launch_bounds__(256)
void raymarch_kernel(const float* __restrict__ camrot,
                     const float* __restrict__ campos,
                     const float* __restrict__ focal,
                     const float* __restrict__ princpt,
                     const float* __restrict__ pixelcoords,
                     float* __restrict__ out) {
    int p = threadIdx.x & 1;                                // 0: z0-plane, 1: z1-plane
    int x = blockIdx.x * 32 + (threadIdx.x >> 1);
    int y = blockIdx.y * blockDim.y + threadIdx.y;
    int b = blockIdx.z;

    // ---- ray setup (bit-exact IEEE ops: no fma contraction, real div/sqrt) ----
    const float* pc = pixelcoords + (((size_t)b * HH + y) * WW + x) * 2;
    float vx = __fdiv_rn(__fsub_rn(pc[0], princpt[b * 2 + 0]), focal[b * 2 + 0]);
    float vy = __fdiv_rn(__fsub_rn(pc[1], princpt[b * 2 + 1]), focal[b * 2 + 1]);

    const float* R = camrot + b * 9;   // world_j = sum_i R[i][j] * v_i
    float dx = __fadd_rn(__fadd_rn(__fmul_rn(R[0], vx), __fmul_rn(R[3], vy)), R[6]);
    float dy = __fadd_rn(__fadd_rn(__fmul_rn(R[1], vx), __fmul_rn(R[4], vy)), R[7]);
    float dz = __fadd_rn(__fadd_rn(__fmul_rn(R[2], vx), __fmul_rn(R[5], vy)), R[8]);

    float n2 = __fadd_rn(__fadd_rn(__fmul_rn(dx, dx), __fmul_rn(dy, dy)),
                         __fmul_rn(dz, dz));
    float nr = __fsqrt_rn(n2);
    dx = __fdiv_rn(dx, nr);
    dy = __fdiv_rn(dy, nr);
    dz = __fdiv_rn(dz, nr);

    float cx = campos[b * 3 + 0];
    float cy = campos[b * 3 + 1];
    float cz = campos[b * 3 + 2];

    // ---- ray-AABB intersection with [-1,1]^3 (exact divides; inf on /0) ----
    float t1x = __fdiv_rn(__fsub_rn(-1.0f, cx), dx);
    float t2x = __fdiv_rn(__fsub_rn( 1.0f, cx), dx);
    float t1y = __fdiv_rn(__fsub_rn(-1.0f, cy), dy);
    float t2y = __fdiv_rn(__fsub_rn( 1.0f, cy), dy);
    float t1z = __fdiv_rn(__fsub_rn(-1.0f, cz), dz);
    float t2z = __fdiv_rn(__fsub_rn( 1.0f, cz), dz);
    float tmin = fmaxf(fminf(t1x, t2x), fmaxf(fminf(t1y, t2y), fminf(t1z, t2z)));
    float tmax = fminf(fmaxf(t1x, t2x), fminf(fmaxf(t1y, t2y), fmaxf(t1z, t2z)));

    float r = 0.0f, g = 0.0f, bl = 0.0f, alpha = 0.0f;
    size_t obase = ((size_t)b * 4) * HH * WW + (size_t)y * WW + x;

    bool hit = tmin < tmax;
    if (hit && tmax > 0.0f) {
        float t0 = fmaxf(tmin, 0.0f);
        float px = __fadd_rn(cx, __fmul_rn(dx, t0));
        float py = __fadd_rn(cy, __fmul_rn(dy, t0));
        float pz = __fadd_rn(cz, __fmul_rn(dz, t0));
        // DT = 2^-5 exactly -> d*DT exact, step adds bit-identical to reference
        float sx = __fmul_rn(dx, DT);
        float sy = __fmul_rn(dy, DT);
        float sz = __fmul_rn(dz, DT);

        const uint2* __restrict__ vb = g_vol + (size_t)b * DDD + p * (DV * DV);
        bool entered = false;

        #pragma unroll 1
        for (int s = 0; s < NSTEPS; ++s) {
            bool valid = (px > -1.0f) & (px < 1.0f) &
                         (py > -1.0f) & (py < 1.0f) &
                         (pz > -1.0f) & (pz < 1.0f);
            if (valid) {
                entered = true;
                float gx = fminf(fmaxf((px + 1.0f) * 0.5f * 127.0f, 0.0f), 127.0f);
                float gy = fminf(fmaxf((py + 1.0f) * 0.5f * 127.0f, 0.0f), 127.0f);
                float gz = fminf(fmaxf((pz + 1.0f) * 0.5f * 127.0f, 0.0f), 127.0f);
                int ix = min((int)gx, DV - 2);
                int iy = min((int)gy, DV - 2);
                int iz = min((int)gz, DV - 2);
                float fx = gx - (float)ix;
                float fy = gy - (float)iy;
                float fz = gz - (float)iz;

                // this lane loads the 4 corners of its z-plane (iz + p)
                int idx = (iz * DV + iy) * DV + ix;
                float4 c00 = load4h(vb, idx);
                float4 c01 = load4h(vb, idx + 1);
                float4 c10 = load4h(vb, idx + DV);
                float4 c11 = load4h(vb, idx + DV + 1);

                float4 a0 = lerp4(c00, c01, fx);
                float4 a1 = lerp4(c10, c11, fx);
                float4 cp = lerp4(a0, a1, fy);         // bilinear result of plane iz+p

                // exchange with the sibling lane (identical control flow ->
                // the pair is always co-active in activemask)
                unsigned m = __activemask();
                float4 cq;
                cq.x = __shfl_xor_sync(m, cp.x, 1);
                cq.y = __shfl_xor_sync(m, cp.y, 1);
                cq.z = __shfl_xor_sync(m, cp.z, 1);
                cq.w = __shfl_xor_sync(m, cp.w, 1);

                // z-lerp as a symmetric weighted sum: both lanes compute the
                // SAME two products then a commutative add -> bit-identical
                // alpha across the pair (required to keep the break in sync).
                float omfz = 1.0f - fz;
                float wSelf  = (p == 0) ? omfz : fz;
                float wOther = (p == 0) ? fz : omfz;
                float4 smp;
                smp.x = __fadd_rn(__fmul_rn(cp.x, wSelf), __fmul_rn(cq.x, wOther));
                smp.y = __fadd_rn(__fmul_rn(cp.y, wSelf), __fmul_rn(cq.y, wOther));
                smp.z = __fadd_rn(__fmul_rn(cp.z, wSelf), __fmul_rn(cq.z, wOther));
                smp.w = __fadd_rn(__fmul_rn(cp.w, wSelf), __fmul_rn(cq.w, wOther));

                // contrib = min(alpha + sigma*DT, 1) - alpha   (sigma*DT exact)
                float contrib = __fsub_rn(fminf(__fadd_rn(alpha, __fmul_rn(smp.w, DT)), 1.0f),
                                          alpha);
                r  = __fadd_rn(r,  __fmul_rn(smp.x, contrib));
                g  = __fadd_rn(g,  __fmul_rn(smp.y, contrib));
                bl = __fadd_rn(bl, __fmul_rn(smp.z, contrib));
                alpha = __fadd_rn(alpha, contrib);
                if (alpha >= 1.0f) break;   // contrib exactly 0 from here on
            } else if (entered) {
                break;                       // convex box: left for good
            }
            px = __fadd_rn(px, sx);
            py = __fadd_rn(py, sy);
            pz = __fadd_rn(pz, sz);
        }
    }

    if (p == 0) {
        out[obase]               = r;
        out[obase + HH * WW]     = g;
        out[obase + 2 * HH * WW] = bl;
        out[obase + 3 * HH * WW] = alpha;
    }
}

extern "C" void kernel_launch(void* const* d_in, const int* in_sizes, int n_in,
                              void* d_out, int out_size) {
    const float* camrot      = (const float*)d_in[0];
    const float* campos      = (const float*)d_in[1];
    const float* focal       = (const float*)d_in[2];
    const float* princpt     = (const float*)d_in[3];
    const float* pixelcoords = (const float*)d_in[4];
    const float* volume      = (const float*)d_in[5];
    float* out = (float*)d_out;

    int nvox = BB * DDD;
    permute_kernel<<<(nvox + 255) / 256, 256>>>(volume);

    dim3 block(64, 4, 1);                 // 256 threads = 128 rays (2 threads/ray)
    dim3 grid(WW / 32, HH / 4, BB);       // 8 x 64 x 2 = 1024 blocks
    raymarch_kernel<<<grid, block>>>(camrot, campos, focal, princpt,
                                     pixelcoords, out);
}

// round 6
// speedup vs baseline: 1.7098x; 1.1561x over previous
#include <cuda_runtime.h>
#include <cuda_fp16.h>

#define DV 128
#define HH 256
#define WW 256
#define BB 2
#define NSTEPS 111
#define DT 0.03125f
#define DDD (DV*DV*DV)

// Static device scratch: volume permuted to AoS half4 (r,g | b,sigma) per voxel,
// packed in a uint2 (8 bytes). 2 * 128^3 * 8B = 32 MB.
__device__ uint2 g_vol[BB * DDD];

__global__ void permute_kernel(const float* __restrict__ vol) {
    int i = blockIdx.x * blockDim.x + threadIdx.x;
    if (i >= BB * DDD) return;
    int b = i / DDD;
    int v = i - b * DDD;
    const float* p = vol + (size_t)b * 4 * DDD + v;
    __half2 lo = __floats2half2_rn(p[0], p[DDD]);
    __half2 hi = __floats2half2_rn(p[2 * DDD], p[3 * DDD]);
    uint2 out;
    out.x = *reinterpret_cast<unsigned*>(&lo);
    out.y = *reinterpret_cast<unsigned*>(&hi);
    g_vol[i] = out;
}

__device__ __forceinline__ __half2 h2lerp(__half2 a, __half2 b, __half2 f, __half2 omf) {
    return __hfma2(b, f, __hmul2(a, omf));
}

// blockDim = (64, 4): lane pair (2k, 2k+1) processes one ray; parity = z-plane.
__global__ __launch_bounds__(256)
void raymarch_kernel(const float* __restrict__ camrot,
                     const float* __restrict__ campos,
                     const float* __restrict__ focal,
                     const float* __restrict__ princpt,
                     const float* __restrict__ pixelcoords,
                     float* __restrict__ out) {
    int p = threadIdx.x & 1;                                // 0: z0-plane, 1: z1-plane
    int x = blockIdx.x * 32 + (threadIdx.x >> 1);
    int y = blockIdx.y * blockDim.y + threadIdx.y;
    int b = blockIdx.z;

    // ---- ray setup (bit-exact IEEE ops: no fma contraction, real div/sqrt) ----
    const float* pc = pixelcoords + (((size_t)b * HH + y) * WW + x) * 2;
    float vx = __fdiv_rn(__fsub_rn(pc[0], princpt[b * 2 + 0]), focal[b * 2 + 0]);
    float vy = __fdiv_rn(__fsub_rn(pc[1], princpt[b * 2 + 1]), focal[b * 2 + 1]);

    const float* R = camrot + b * 9;   // world_j = sum_i R[i][j] * v_i
    float dx = __fadd_rn(__fadd_rn(__fmul_rn(R[0], vx), __fmul_rn(R[3], vy)), R[6]);
    float dy = __fadd_rn(__fadd_rn(__fmul_rn(R[1], vx), __fmul_rn(R[4], vy)), R[7]);
    float dz = __fadd_rn(__fadd_rn(__fmul_rn(R[2], vx), __fmul_rn(R[5], vy)), R[8]);

    float n2 = __fadd_rn(__fadd_rn(__fmul_rn(dx, dx), __fmul_rn(dy, dy)),
                         __fmul_rn(dz, dz));
    float nr = __fsqrt_rn(n2);
    dx = __fdiv_rn(dx, nr);
    dy = __fdiv_rn(dy, nr);
    dz = __fdiv_rn(dz, nr);

    float cx = campos[b * 3 + 0];
    float cy = campos[b * 3 + 1];
    float cz = campos[b * 3 + 2];

    // ---- ray-AABB intersection with [-1,1]^3 (exact divides; inf on /0) ----
    float t1x = __fdiv_rn(__fsub_rn(-1.0f, cx), dx);
    float t2x = __fdiv_rn(__fsub_rn( 1.0f, cx), dx);
    float t1y = __fdiv_rn(__fsub_rn(-1.0f, cy), dy);
    float t2y = __fdiv_rn(__fsub_rn( 1.0f, cy), dy);
    float t1z = __fdiv_rn(__fsub_rn(-1.0f, cz), dz);
    float t2z = __fdiv_rn(__fsub_rn( 1.0f, cz), dz);
    float tmin = fmaxf(fminf(t1x, t2x), fmaxf(fminf(t1y, t2y), fminf(t1z, t2z)));
    float tmax = fminf(fmaxf(t1x, t2x), fminf(fmaxf(t1y, t2y), fmaxf(t1z, t2z)));

    float r = 0.0f, g = 0.0f, bl = 0.0f, alpha = 0.0f;
    size_t obase = ((size_t)b * 4) * HH * WW + (size_t)y * WW + x;

    bool hit = tmin < tmax;
    if (hit && tmax > 0.0f) {
        float t0 = fmaxf(tmin, 0.0f);
        float px = __fadd_rn(cx, __fmul_rn(dx, t0));
        float py = __fadd_rn(cy, __fmul_rn(dy, t0));
        float pz = __fadd_rn(cz, __fmul_rn(dz, t0));
        // DT = 2^-5 exactly -> d*DT exact, step adds bit-identical to reference
        float sx = __fmul_rn(dx, DT);
        float sy = __fmul_rn(dy, DT);
        float sz = __fmul_rn(dz, DT);

        const uint2* __restrict__ vb = g_vol + (size_t)b * DDD + p * (DV * DV);
        bool entered = false;

        #pragma unroll 1
        for (int s = 0; s < NSTEPS; ++s) {
            bool valid = (px > -1.0f) & (px < 1.0f) &
                         (py > -1.0f) & (py < 1.0f) &
                         (pz > -1.0f) & (pz < 1.0f);
            if (valid) {
                entered = true;
                // coord map: (p+1)*0.5*127 == p*63.5 + 63.5 (continuous path only)
                float gx = fminf(fmaxf(__fmaf_rn(px, 63.5f, 63.5f), 0.0f), 127.0f);
                float gy = fminf(fmaxf(__fmaf_rn(py, 63.5f, 63.5f), 0.0f), 127.0f);
                float gz = fminf(fmaxf(__fmaf_rn(pz, 63.5f, 63.5f), 0.0f), 127.0f);
                int ix = min((int)gx, DV - 2);
                int iy = min((int)gy, DV - 2);
                int iz = min((int)gz, DV - 2);
                float fx = gx - (float)ix;
                float fy = gy - (float)iy;
                float fz = gz - (float)iz;

                // this lane loads the 4 corners of its z-plane (iz + p), packed half2
                int idx = (iz * DV + iy) * DV + ix;
                uint2 r00 = __ldg(vb + idx);
                uint2 r01 = __ldg(vb + idx + 1);
                uint2 r10 = __ldg(vb + idx + DV);
                uint2 r11 = __ldg(vb + idx + DV + 1);
                __half2 c00a = *reinterpret_cast<__half2*>(&r00.x);
                __half2 c00b = *reinterpret_cast<__half2*>(&r00.y);
                __half2 c01a = *reinterpret_cast<__half2*>(&r01.x);
                __half2 c01b = *reinterpret_cast<__half2*>(&r01.y);
                __half2 c10a = *reinterpret_cast<__half2*>(&r10.x);
                __half2 c10b = *reinterpret_cast<__half2*>(&r10.y);
                __half2 c11a = *reinterpret_cast<__half2*>(&r11.x);
                __half2 c11b = *reinterpret_cast<__half2*>(&r11.y);

                // packed bilinear (x then y) in half2
                __half2 fxh  = __float2half2_rn(fx);
                __half2 ofxh = __float2half2_rn(1.0f - fx);
                __half2 fyh  = __float2half2_rn(fy);
                __half2 ofyh = __float2half2_rn(1.0f - fy);

                __half2 a0a = h2lerp(c00a, c01a, fxh, ofxh);
                __half2 a0b = h2lerp(c00b, c01b, fxh, ofxh);
                __half2 a1a = h2lerp(c10a, c11a, fxh, ofxh);
                __half2 a1b = h2lerp(c10b, c11b, fxh, ofxh);
                __half2 cpa = h2lerp(a0a, a1a, fyh, ofyh);   // (r,g) of plane iz+p
                __half2 cpb = h2lerp(a0b, a1b, fyh, ofyh);   // (b,sigma)

                // exchange with sibling lane: 2 packed shuffles
                unsigned m = __activemask();
                unsigned cpa_u = *reinterpret_cast<unsigned*>(&cpa);
                unsigned cpb_u = *reinterpret_cast<unsigned*>(&cpb);
                unsigned cqa_u = __shfl_xor_sync(m, cpa_u, 1);
                unsigned cqb_u = __shfl_xor_sync(m, cpb_u, 1);
                __half2 cqa = *reinterpret_cast<__half2*>(&cqa_u);
                __half2 cqb = *reinterpret_cast<__half2*>(&cqb_u);

                // z-lerp, symmetric: same two rounded products + commutative add
                // on both lanes -> smp (and alpha) bit-identical across the pair
                __half2 fzh  = __float2half2_rn(fz);
                __half2 ofzh = __float2half2_rn(1.0f - fz);
                __half2 wSelf  = (p == 0) ? ofzh : fzh;
                __half2 wOther = (p == 0) ? fzh : ofzh;
                __half2 smpa = __hadd2(__hmul2(cpa, wSelf), __hmul2(cqa, wOther));
                __half2 smpb = __hadd2(__hmul2(cpb, wSelf), __hmul2(cqb, wOther));

                float2 rg = __half22float2(smpa);
                float2 ba = __half22float2(smpb);

                // contrib = min(alpha + sigma*DT, 1) - alpha   (sigma*DT exact)
                float contrib = __fsub_rn(fminf(__fadd_rn(alpha, __fmul_rn(ba.y, DT)), 1.0f),
                                          alpha);
                r  = __fadd_rn(r,  __fmul_rn(rg.x, contrib));
                g  = __fadd_rn(g,  __fmul_rn(rg.y, contrib));
                bl = __fadd_rn(bl, __fmul_rn(ba.x, contrib));
                alpha = __fadd_rn(alpha, contrib);
                if (alpha >= 1.0f) break;   // contrib exactly 0 from here on
            } else if (entered) {
                break;                       // convex box: left for good
            }
            px = __fadd_rn(px, sx);
            py = __fadd_rn(py, sy);
            pz = __fadd_rn(pz, sz);
        }
    }

    if (p == 0) {
        out[obase]               = r;
        out[obase + HH * WW]     = g;
        out[obase + 2 * HH * WW] = bl;
        out[obase + 3 * HH * WW] = alpha;
    }
}

extern "C" void kernel_launch(void* const* d_in, const int* in_sizes, int n_in,
                              void* d_out, int out_size) {
    const float* camrot      = (const float*)d_in[0];
    const float* campos      = (const float*)d_in[1];
    const float* focal       = (const float*)d_in[2];
    const float* princpt     = (const float*)d_in[3];
    const float* pixelcoords = (const float*)d_in[4];
    const float* volume      = (const float*)d_in[5];
    float* out = (float*)d_out;

    int nvox = BB * DDD;
    permute_kernel<<<(nvox + 255) / 256, 256>>>(volume);

    dim3 block(64, 4, 1);                 // 256 threads = 128 rays (2 threads/ray)
    dim3 grid(WW / 32, HH / 4, BB);       // 8 x 64 x 2 = 1024 blocks
    raymarch_kernel<<<grid, block>>>(camrot, campos, focal, princpt,
                                     pixelcoords, out);
}

// round 7
// speedup vs baseline: 1.9356x; 1.1320x over previous
#include <cuda_runtime.h>
#include <cuda_fp16.h>

#define DV 128
#define HH 256
#define WW 256
#define BB 2
#define NSTEPS 111
#define DT 0.03125f
#define DDD (DV*DV*DV)

// Static device scratch: volume permuted to AoS half4 (r,g | b,sigma) per voxel
// (8B each), stored as uint4 pairs for 16B-aligned stores. 32 MB total.
__device__ uint4 g_vol[BB * DDD / 2];

// 4 voxels per thread: 4 coalesced float4 loads (one per channel stream),
// 2 uint4 stores.
__global__ void permute_kernel(const float4* __restrict__ vol) {
    int i = blockIdx.x * blockDim.x + threadIdx.x;     // quad index
    const int QPB = DDD / 4;                           // quads per batch
    if (i >= BB * QPB) return;
    int b = i / QPB;
    int v = i - b * QPB;
    const float4* base = vol + (size_t)b * DDD;        // DDD float4 per batch (4*DDD floats)
    float4 c0 = __ldg(base + 0 * QPB + v);
    float4 c1 = __ldg(base + 1 * QPB + v);
    float4 c2 = __ldg(base + 2 * QPB + v);
    float4 c3 = __ldg(base + 3 * QPB + v);

    __half2 p0l = __floats2half2_rn(c0.x, c1.x), p0h = __floats2half2_rn(c2.x, c3.x);
    __half2 p1l = __floats2half2_rn(c0.y, c1.y), p1h = __floats2half2_rn(c2.y, c3.y);
    __half2 p2l = __floats2half2_rn(c0.z, c1.z), p2h = __floats2half2_rn(c2.z, c3.z);
    __half2 p3l = __floats2half2_rn(c0.w, c1.w), p3h = __floats2half2_rn(c2.w, c3.w);

    uint4 s0, s1;
    s0.x = *reinterpret_cast<unsigned*>(&p0l); s0.y = *reinterpret_cast<unsigned*>(&p0h);
    s0.z = *reinterpret_cast<unsigned*>(&p1l); s0.w = *reinterpret_cast<unsigned*>(&p1h);
    s1.x = *reinterpret_cast<unsigned*>(&p2l); s1.y = *reinterpret_cast<unsigned*>(&p2h);
    s1.z = *reinterpret_cast<unsigned*>(&p3l); s1.w = *reinterpret_cast<unsigned*>(&p3h);

    g_vol[(size_t)b * (DDD / 2) + 2 * v]     = s0;
    g_vol[(size_t)b * (DDD / 2) + 2 * v + 1] = s1;
}

__device__ __forceinline__ __half2 h2lerp(__half2 a, __half2 b, __half2 f, __half2 omf) {
    return __hfma2(b, f, __hmul2(a, omf));
}

// blockDim = (64, 4): lane pair (2k, 2k+1) processes one ray; parity = z-plane.
__global__ __launch_bounds__(256)
void raymarch_kernel(const float* __restrict__ camrot,
                     const float* __restrict__ campos,
                     const float* __restrict__ focal,
                     const float* __restrict__ princpt,
                     const float* __restrict__ pixelcoords,
                     float* __restrict__ out) {
    int p = threadIdx.x & 1;                                // 0: z0-plane, 1: z1-plane
    int x = blockIdx.x * 32 + (threadIdx.x >> 1);
    int y = blockIdx.y * blockDim.y + threadIdx.y;
    int b = blockIdx.z;

    // ---- ray setup (bit-exact IEEE ops: no fma contraction, real div/sqrt) ----
    const float* pc = pixelcoords + (((size_t)b * HH + y) * WW + x) * 2;
    float vx = __fdiv_rn(__fsub_rn(pc[0], princpt[b * 2 + 0]), focal[b * 2 + 0]);
    float vy = __fdiv_rn(__fsub_rn(pc[1], princpt[b * 2 + 1]), focal[b * 2 + 1]);

    const float* R = camrot + b * 9;   // world_j = sum_i R[i][j] * v_i
    float dx = __fadd_rn(__fadd_rn(__fmul_rn(R[0], vx), __fmul_rn(R[3], vy)), R[6]);
    float dy = __fadd_rn(__fadd_rn(__fmul_rn(R[1], vx), __fmul_rn(R[4], vy)), R[7]);
    float dz = __fadd_rn(__fadd_rn(__fmul_rn(R[2], vx), __fmul_rn(R[5], vy)), R[8]);

    float n2 = __fadd_rn(__fadd_rn(__fmul_rn(dx, dx), __fmul_rn(dy, dy)),
                         __fmul_rn(dz, dz));
    float nr = __fsqrt_rn(n2);
    dx = __fdiv_rn(dx, nr);
    dy = __fdiv_rn(dy, nr);
    dz = __fdiv_rn(dz, nr);

    float cx = campos[b * 3 + 0];
    float cy = campos[b * 3 + 1];
    float cz = campos[b * 3 + 2];

    // ---- ray-AABB intersection with [-1,1]^3 (exact divides; inf on /0) ----
    float t1x = __fdiv_rn(__fsub_rn(-1.0f, cx), dx);
    float t2x = __fdiv_rn(__fsub_rn( 1.0f, cx), dx);
    float t1y = __fdiv_rn(__fsub_rn(-1.0f, cy), dy);
    float t2y = __fdiv_rn(__fsub_rn( 1.0f, cy), dy);
    float t1z = __fdiv_rn(__fsub_rn(-1.0f, cz), dz);
    float t2z = __fdiv_rn(__fsub_rn( 1.0f, cz), dz);
    float tmin = fmaxf(fminf(t1x, t2x), fmaxf(fminf(t1y, t2y), fminf(t1z, t2z)));
    float tmax = fminf(fmaxf(t1x, t2x), fminf(fmaxf(t1y, t2y), fmaxf(t1z, t2z)));

    float r = 0.0f, g = 0.0f, bl = 0.0f, alpha = 0.0f;
    size_t obase = ((size_t)b * 4) * HH * WW + (size_t)y * WW + x;

    bool hit = tmin < tmax;
    if (hit && tmax > 0.0f) {
        float t0 = fmaxf(tmin, 0.0f);
        float px = __fadd_rn(cx, __fmul_rn(dx, t0));
        float py = __fadd_rn(cy, __fmul_rn(dy, t0));
        float pz = __fadd_rn(cz, __fmul_rn(dz, t0));
        // DT = 2^-5 exactly -> d*DT exact, step adds bit-identical to reference
        float sx = __fmul_rn(dx, DT);
        float sy = __fmul_rn(dy, DT);
        float sz = __fmul_rn(dz, DT);

        const uint2* __restrict__ vb =
            reinterpret_cast<const uint2*>(g_vol) + (size_t)b * DDD + p * (DV * DV);
        bool entered = false;
        const __half2 oneh = __float2half2_rn(1.0f);

        #pragma unroll 1
        for (int s = 0; s < NSTEPS; ++s) {
            // |p|<1 is bit-equivalent to (p>-1)&(p<1) here (no NaNs); FSETP
            // absorbs the abs for free -> 3 compares instead of 6
            bool valid = (fabsf(px) < 1.0f) & (fabsf(py) < 1.0f) & (fabsf(pz) < 1.0f);
            if (valid) {
                entered = true;
                // valid => px in (-1,1) => gx in [0,127] after rounding; no clamp
                float gx = __fmaf_rn(px, 63.5f, 63.5f);
                float gy = __fmaf_rn(py, 63.5f, 63.5f);
                float gz = __fmaf_rn(pz, 63.5f, 63.5f);
                int ix = min((int)gx, DV - 2);
                int iy = min((int)gy, DV - 2);
                int iz = min((int)gz, DV - 2);
                float fx = gx - (float)ix;
                float fy = gy - (float)iy;
                float fz = gz - (float)iz;

                // this lane loads the 4 corners of its z-plane (iz + p), packed half2
                int idx = (iz * DV + iy) * DV + ix;
                uint2 r00 = __ldg(vb + idx);
                uint2 r01 = __ldg(vb + idx + 1);
                uint2 r10 = __ldg(vb + idx + DV);
                uint2 r11 = __ldg(vb + idx + DV + 1);
                __half2 c00a = *reinterpret_cast<__half2*>(&r00.x);
                __half2 c00b = *reinterpret_cast<__half2*>(&r00.y);
                __half2 c01a = *reinterpret_cast<__half2*>(&r01.x);
                __half2 c01b = *reinterpret_cast<__half2*>(&r01.y);
                __half2 c10a = *reinterpret_cast<__half2*>(&r10.x);
                __half2 c10b = *reinterpret_cast<__half2*>(&r10.y);
                __half2 c11a = *reinterpret_cast<__half2*>(&r11.x);
                __half2 c11b = *reinterpret_cast<__half2*>(&r11.y);

                // packed bilinear (x then y) in half2; complements in half
                __half2 fxh  = __float2half2_rn(fx);
                __half2 ofxh = __hsub2(oneh, fxh);
                __half2 fyh  = __float2half2_rn(fy);
                __half2 ofyh = __hsub2(oneh, fyh);

                __half2 a0a = h2lerp(c00a, c01a, fxh, ofxh);
                __half2 a0b = h2lerp(c00b, c01b, fxh, ofxh);
                __half2 a1a = h2lerp(c10a, c11a, fxh, ofxh);
                __half2 a1b = h2lerp(c10b, c11b, fxh, ofxh);
                __half2 cpa = h2lerp(a0a, a1a, fyh, ofyh);   // (r,g) of plane iz+p
                __half2 cpb = h2lerp(a0b, a1b, fyh, ofyh);   // (b,sigma)

                // exchange with sibling lane: 2 packed shuffles
                unsigned m = __activemask();
                unsigned cpa_u = *reinterpret_cast<unsigned*>(&cpa);
                unsigned cpb_u = *reinterpret_cast<unsigned*>(&cpb);
                unsigned cqa_u = __shfl_xor_sync(m, cpa_u, 1);
                unsigned cqb_u = __shfl_xor_sync(m, cpb_u, 1);
                __half2 cqa = *reinterpret_cast<__half2*>(&cqa_u);
                __half2 cqb = *reinterpret_cast<__half2*>(&cqb_u);

                // z-lerp, symmetric: same two rounded products + commutative add
                // on both lanes -> smp (and alpha) bit-identical across the pair
                __half2 fzh  = __float2half2_rn(fz);
                __half2 ofzh = __hsub2(oneh, fzh);
                __half2 wSelf  = (p == 0) ? ofzh : fzh;
                __half2 wOther = (p == 0) ? fzh : ofzh;
                __half2 smpa = __hadd2(__hmul2(cpa, wSelf), __hmul2(cqa, wOther));
                __half2 smpb = __hadd2(__hmul2(cpb, wSelf), __hmul2(cqb, wOther));

                float2 rg = __half22float2(smpa);
                float2 ba = __half22float2(smpb);

                // contrib = min(alpha + sigma*DT, 1) - alpha   (sigma*DT exact)
                float contrib = __fsub_rn(fminf(__fadd_rn(alpha, __fmul_rn(ba.y, DT)), 1.0f),
                                          alpha);
                r  = __fadd_rn(r,  __fmul_rn(rg.x, contrib));
                g  = __fadd_rn(g,  __fmul_rn(rg.y, contrib));
                bl = __fadd_rn(bl, __fmul_rn(ba.x, contrib));
                alpha = __fadd_rn(alpha, contrib);
                if (alpha >= 1.0f) break;   // contrib exactly 0 from here on
            } else if (entered) {
                break;                       // convex box: left for good
            }
            px = __fadd_rn(px, sx);
            py = __fadd_rn(py, sy);
            pz = __fadd_rn(pz, sz);
        }
    }

    if (p == 0) {
        out[obase]               = r;
        out[obase + HH * WW]     = g;
        out[obase + 2 * HH * WW] = bl;
        out[obase + 3 * HH * WW] = alpha;
    }
}

extern "C" void kernel_launch(void* const* d_in, const int* in_sizes, int n_in,
                              void* d_out, int out_size) {
    const float* camrot      = (const float*)d_in[0];
    const float* campos      = (const float*)d_in[1];
    const float* focal       = (const float*)d_in[2];
    const float* princpt     = (const float*)d_in[3];
    const float* pixelcoords = (const float*)d_in[4];
    const float* volume      = (const float*)d_in[5];
    float* out = (float*)d_out;

    int nquads = BB * DDD / 4;
    permute_kernel<<<(nquads + 255) / 256, 256>>>((const float4*)volume);

    dim3 block(64, 4, 1);                 // 256 threads = 128 rays (2 threads/ray)
    dim3 grid(WW / 32, HH / 4, BB);       // 8 x 64 x 2 = 1024 blocks
    raymarch_kernel<<<grid, block>>>(camrot, campos, focal, princpt,
                                     pixelcoords, out);
}

// round 8
// speedup vs baseline: 2.0513x; 1.0598x over previous
#include <cuda_runtime.h>
#include <cuda_fp16.h>

#define DV 128
#define HH 256
#define WW 256
#define BB 2
#define NSTEPS 111
#define DT 0.03125f
#define DDD (DV*DV*DV)

// Static device scratch: volume permuted to AoS half4 (r,g | b,sigma) per voxel
// (8B each), stored as uint4 pairs for 16B-aligned stores. 32 MB total.
__device__ uint4 g_vol[BB * DDD / 2];

// 4 voxels per thread: 4 coalesced float4 loads (one per channel stream),
// 2 uint4 stores.
__global__ void permute_kernel(const float4* __restrict__ vol) {
    int i = blockIdx.x * blockDim.x + threadIdx.x;     // quad index
    const int QPB = DDD / 4;                           // quads per batch
    if (i >= BB * QPB) return;
    int b = i / QPB;
    int v = i - b * QPB;
    const float4* base = vol + (size_t)b * DDD;        // DDD float4 per batch
    float4 c0 = __ldg(base + 0 * QPB + v);
    float4 c1 = __ldg(base + 1 * QPB + v);
    float4 c2 = __ldg(base + 2 * QPB + v);
    float4 c3 = __ldg(base + 3 * QPB + v);

    __half2 p0l = __floats2half2_rn(c0.x, c1.x), p0h = __floats2half2_rn(c2.x, c3.x);
    __half2 p1l = __floats2half2_rn(c0.y, c1.y), p1h = __floats2half2_rn(c2.y, c3.y);
    __half2 p2l = __floats2half2_rn(c0.z, c1.z), p2h = __floats2half2_rn(c2.z, c3.z);
    __half2 p3l = __floats2half2_rn(c0.w, c1.w), p3h = __floats2half2_rn(c2.w, c3.w);

    uint4 s0, s1;
    s0.x = *reinterpret_cast<unsigned*>(&p0l); s0.y = *reinterpret_cast<unsigned*>(&p0h);
    s0.z = *reinterpret_cast<unsigned*>(&p1l); s0.w = *reinterpret_cast<unsigned*>(&p1h);
    s1.x = *reinterpret_cast<unsigned*>(&p2l); s1.y = *reinterpret_cast<unsigned*>(&p2h);
    s1.z = *reinterpret_cast<unsigned*>(&p3l); s1.w = *reinterpret_cast<unsigned*>(&p3h);

    g_vol[(size_t)b * (DDD / 2) + 2 * v]     = s0;
    g_vol[(size_t)b * (DDD / 2) + 2 * v + 1] = s1;
}

// blockDim = (64, 4): lane pair (2k, 2k+1) processes one ray; parity = z-plane.
__global__ __launch_bounds__(256)
void raymarch_kernel(const float* __restrict__ camrot,
                     const float* __restrict__ campos,
                     const float* __restrict__ focal,
                     const float* __restrict__ princpt,
                     const float* __restrict__ pixelcoords,
                     float* __restrict__ out) {
    int p = threadIdx.x & 1;                                // 0: z0-plane, 1: z1-plane
    int x = blockIdx.x * 32 + (threadIdx.x >> 1);
    int y = blockIdx.y * blockDim.y + threadIdx.y;
    int b = blockIdx.z;

    // ---- ray setup (bit-exact IEEE ops: no fma contraction, real div/sqrt) ----
    const float* pc = pixelcoords + (((size_t)b * HH + y) * WW + x) * 2;
    float vx = __fdiv_rn(__fsub_rn(pc[0], princpt[b * 2 + 0]), focal[b * 2 + 0]);
    float vy = __fdiv_rn(__fsub_rn(pc[1], princpt[b * 2 + 1]), focal[b * 2 + 1]);

    const float* R = camrot + b * 9;   // world_j = sum_i R[i][j] * v_i
    float dx = __fadd_rn(__fadd_rn(__fmul_rn(R[0], vx), __fmul_rn(R[3], vy)), R[6]);
    float dy = __fadd_rn(__fadd_rn(__fmul_rn(R[1], vx), __fmul_rn(R[4], vy)), R[7]);
    float dz = __fadd_rn(__fadd_rn(__fmul_rn(R[2], vx), __fmul_rn(R[5], vy)), R[8]);

    float n2 = __fadd_rn(__fadd_rn(__fmul_rn(dx, dx), __fmul_rn(dy, dy)),
                         __fmul_rn(dz, dz));
    float nr = __fsqrt_rn(n2);
    dx = __fdiv_rn(dx, nr);
    dy = __fdiv_rn(dy, nr);
    dz = __fdiv_rn(dz, nr);

    float cx = campos[b * 3 + 0];
    float cy = campos[b * 3 + 1];
    float cz = campos[b * 3 + 2];

    // ---- ray-AABB intersection with [-1,1]^3 (exact divides; inf on /0) ----
    float t1x = __fdiv_rn(__fsub_rn(-1.0f, cx), dx);
    float t2x = __fdiv_rn(__fsub_rn( 1.0f, cx), dx);
    float t1y = __fdiv_rn(__fsub_rn(-1.0f, cy), dy);
    float t2y = __fdiv_rn(__fsub_rn( 1.0f, cy), dy);
    float t1z = __fdiv_rn(__fsub_rn(-1.0f, cz), dz);
    float t2z = __fdiv_rn(__fsub_rn( 1.0f, cz), dz);
    float tmin = fmaxf(fminf(t1x, t2x), fmaxf(fminf(t1y, t2y), fminf(t1z, t2z)));
    float tmax = fminf(fmaxf(t1x, t2x), fminf(fmaxf(t1y, t2y), fmaxf(t1z, t2z)));

    float r = 0.0f, g = 0.0f, bl = 0.0f, alpha = 0.0f;
    size_t obase = ((size_t)b * 4) * HH * WW + (size_t)y * WW + x;

    bool hit = tmin < tmax;
    if (hit && tmax > 0.0f) {
        float t0 = fmaxf(tmin, 0.0f);
        float px = __fadd_rn(cx, __fmul_rn(dx, t0));
        float py = __fadd_rn(cy, __fmul_rn(dy, t0));
        float pz = __fadd_rn(cz, __fmul_rn(dz, t0));
        // DT = 2^-5 exactly -> d*DT exact, step adds bit-identical to reference
        float sx = __fmul_rn(dx, DT);
        float sy = __fmul_rn(dy, DT);
        float sz = __fmul_rn(dz, DT);

        const uint2* __restrict__ vb =
            reinterpret_cast<const uint2*>(g_vol) + (size_t)b * DDD + p * (DV * DV);
        bool entered = false;

        #pragma unroll 1
        for (int s = 0; s < NSTEPS; ++s) {
            // |p|<1 is bit-equivalent to (p>-1)&(p<1) here (no NaNs)
            bool valid = (fabsf(px) < 1.0f) & (fabsf(py) < 1.0f) & (fabsf(pz) < 1.0f);
            if (valid) {
                entered = true;
                // valid => px in (-1,1) => gx in [0,127] after rounding; no clamp
                float gx = __fmaf_rn(px, 63.5f, 63.5f);
                float gy = __fmaf_rn(py, 63.5f, 63.5f);
                float gz = __fmaf_rn(pz, 63.5f, 63.5f);
                int ix = min((int)gx, DV - 2);
                int iy = min((int)gy, DV - 2);
                int iz = min((int)gz, DV - 2);
                float fx = gx - (float)ix;
                float fy = gy - (float)iy;
                float fz = gz - (float)iz;

                // this lane loads the 4 corners of its z-plane (iz + p), packed half2
                int idx = (iz * DV + iy) * DV + ix;
                uint2 r00 = __ldg(vb + idx);
                uint2 r01 = __ldg(vb + idx + 1);
                uint2 r10 = __ldg(vb + idx + DV);
                uint2 r11 = __ldg(vb + idx + DV + 1);
                __half2 c00a = *reinterpret_cast<__half2*>(&r00.x);
                __half2 c00b = *reinterpret_cast<__half2*>(&r00.y);
                __half2 c01a = *reinterpret_cast<__half2*>(&r01.x);
                __half2 c01b = *reinterpret_cast<__half2*>(&r01.y);
                __half2 c10a = *reinterpret_cast<__half2*>(&r10.x);
                __half2 c10b = *reinterpret_cast<__half2*>(&r10.y);
                __half2 c11a = *reinterpret_cast<__half2*>(&r11.x);
                __half2 c11b = *reinterpret_cast<__half2*>(&r11.y);

                // fp32 corner weights, pre-multiplied by this lane's z-weight.
                // wz(lane0)=1-fz, wz(lane1)=fz  ->  smp = cp + cq is the full
                // trilinear sample.
                float ofx = 1.0f - fx;
                float ofy = 1.0f - fy;
                float wz  = (p == 0) ? (1.0f - fz) : fz;
                float wy0 = ofy * wz;
                float wy1 = fy  * wz;
                __half2 w00 = __float2half2_rn(ofx * wy0);
                __half2 w01 = __float2half2_rn(fx  * wy0);
                __half2 w10 = __float2half2_rn(ofx * wy1);
                __half2 w11 = __float2half2_rn(fx  * wy1);

                // weighted 4-corner sum per packed word (bilinear * z-weight)
                __half2 cpa = __hfma2(c11a, w11,
                              __hfma2(c10a, w10,
                              __hfma2(c01a, w01, __hmul2(c00a, w00))));
                __half2 cpb = __hfma2(c11b, w11,
                              __hfma2(c10b, w10,
                              __hfma2(c01b, w01, __hmul2(c00b, w00))));

                // exchange with sibling lane: 2 packed shuffles
                unsigned m = __activemask();
                unsigned cpa_u = *reinterpret_cast<unsigned*>(&cpa);
                unsigned cpb_u = *reinterpret_cast<unsigned*>(&cpb);
                unsigned cqa_u = __shfl_xor_sync(m, cpa_u, 1);
                unsigned cqb_u = __shfl_xor_sync(m, cpb_u, 1);
                __half2 cqa = *reinterpret_cast<__half2*>(&cqa_u);
                __half2 cqb = *reinterpret_cast<__half2*>(&cqb_u);

                // single commutative add of the identical {cp,cq} pair on both
                // lanes -> smp (and alpha) bit-identical across the pair
                __half2 smpa = __hadd2(cpa, cqa);   // (r,g)
                __half2 smpb = __hadd2(cpb, cqb);   // (b,sigma)

                float2 rg = __half22float2(smpa);
                float2 ba = __half22float2(smpb);

                // contrib = min(alpha + sigma*DT, 1) - alpha   (alpha chain exact)
                float contrib = __fsub_rn(fminf(__fadd_rn(alpha, __fmul_rn(ba.y, DT)), 1.0f),
                                          alpha);
                r  = __fmaf_rn(rg.x, contrib, r);   // rgb: continuous path, fma ok
                g  = __fmaf_rn(rg.y, contrib, g);
                bl = __fmaf_rn(ba.x, contrib, bl);
                alpha = __fadd_rn(alpha, contrib);
                if (alpha >= 1.0f) break;   // contrib exactly 0 from here on
            } else if (entered) {
                break;                       // convex box: left for good
            }
            px = __fadd_rn(px, sx);
            py = __fadd_rn(py, sy);
            pz = __fadd_rn(pz, sz);
        }
    }

    if (p == 0) {
        out[obase]               = r;
        out[obase + HH * WW]     = g;
        out[obase + 2 * HH * WW] = bl;
        out[obase + 3 * HH * WW] = alpha;
    }
}

extern "C" void kernel_launch(void* const* d_in, const int* in_sizes, int n_in,
                              void* d_out, int out_size) {
    const float* camrot      = (const float*)d_in[0];
    const float* campos      = (const float*)d_in[1];
    const float* focal       = (const float*)d_in[2];
    const float* princpt     = (const float*)d_in[3];
    const float* pixelcoords = (const float*)d_in[4];
    const float* volume      = (const float*)d_in[5];
    float* out = (float*)d_out;

    int nquads = BB * DDD / 4;
    permute_kernel<<<(nquads + 255) / 256, 256>>>((const float4*)volume);

    dim3 block(64, 4, 1);                 // 256 threads = 128 rays (2 threads/ray)
    dim3 grid(WW / 32, HH / 4, BB);       // 8 x 64 x 2 = 1024 blocks
    raymarch_kernel<<<grid, block>>>(camrot, campos, focal, princpt,
                                     pixelcoords, out);
}

// round 9
// speedup vs baseline: 2.2003x; 1.0726x over previous
#include <cuda_runtime.h>
#include <cuda_fp16.h>

#define DV 128
#define HH 256
#define WW 256
#define BB 2
#define NSTEPS 111
#define DT 0.03125f
#define DDD (DV*DV*DV)

// Static device scratch: volume permuted to AoS half4 (r,g | b,sigma) per voxel
// (8B each), stored as uint4 pairs for 16B-aligned stores. 32 MB total.
__device__ uint4 g_vol[BB * DDD / 2];

// 4 voxels per thread: 4 coalesced float4 loads (one per channel stream),
// 2 uint4 stores.
__global__ void permute_kernel(const float4* __restrict__ vol) {
    int i = blockIdx.x * blockDim.x + threadIdx.x;     // quad index
    const int QPB = DDD / 4;                           // quads per batch
    if (i >= BB * QPB) return;
    int b = i / QPB;
    int v = i - b * QPB;
    const float4* base = vol + (size_t)b * DDD;        // DDD float4 per batch
    float4 c0 = __ldg(base + 0 * QPB + v);
    float4 c1 = __ldg(base + 1 * QPB + v);
    float4 c2 = __ldg(base + 2 * QPB + v);
    float4 c3 = __ldg(base + 3 * QPB + v);

    __half2 p0l = __floats2half2_rn(c0.x, c1.x), p0h = __floats2half2_rn(c2.x, c3.x);
    __half2 p1l = __floats2half2_rn(c0.y, c1.y), p1h = __floats2half2_rn(c2.y, c3.y);
    __half2 p2l = __floats2half2_rn(c0.z, c1.z), p2h = __floats2half2_rn(c2.z, c3.z);
    __half2 p3l = __floats2half2_rn(c0.w, c1.w), p3h = __floats2half2_rn(c2.w, c3.w);

    uint4 s0, s1;
    s0.x = *reinterpret_cast<unsigned*>(&p0l); s0.y = *reinterpret_cast<unsigned*>(&p0h);
    s0.z = *reinterpret_cast<unsigned*>(&p1l); s0.w = *reinterpret_cast<unsigned*>(&p1h);
    s1.x = *reinterpret_cast<unsigned*>(&p2l); s1.y = *reinterpret_cast<unsigned*>(&p2h);
    s1.z = *reinterpret_cast<unsigned*>(&p3l); s1.w = *reinterpret_cast<unsigned*>(&p3h);

    g_vol[(size_t)b * (DDD / 2) + 2 * v]     = s0;
    g_vol[(size_t)b * (DDD / 2) + 2 * v + 1] = s1;
}

__device__ __forceinline__ unsigned long long packf2(float lo, float hi) {
    unsigned long long r;
    asm("mov.b64 %0, {%1, %2};" : "=l"(r) : "f"(lo), "f"(hi));
    return r;
}
__device__ __forceinline__ void unpackf2(unsigned long long v, float& lo, float& hi) {
    asm("mov.b64 {%0, %1}, %2;" : "=f"(lo), "=f"(hi) : "l"(v));
}

// blockDim = (64, 4): lane pair (2k, 2k+1) processes one ray; parity = z-plane.
__global__ __launch_bounds__(256)
void raymarch_kernel(const float* __restrict__ camrot,
                     const float* __restrict__ campos,
                     const float* __restrict__ focal,
                     const float* __restrict__ princpt,
                     const float* __restrict__ pixelcoords,
                     float* __restrict__ out) {
    int p = threadIdx.x & 1;                                // 0: z0-plane, 1: z1-plane
    int x = blockIdx.x * 32 + (threadIdx.x >> 1);
    int y = blockIdx.y * blockDim.y + threadIdx.y;
    int b = blockIdx.z;

    // ---- ray setup (bit-exact IEEE ops: no fma contraction, real div/sqrt) ----
    const float* pc = pixelcoords + (((size_t)b * HH + y) * WW + x) * 2;
    float vx = __fdiv_rn(__fsub_rn(pc[0], princpt[b * 2 + 0]), focal[b * 2 + 0]);
    float vy = __fdiv_rn(__fsub_rn(pc[1], princpt[b * 2 + 1]), focal[b * 2 + 1]);

    const float* R = camrot + b * 9;   // world_j = sum_i R[i][j] * v_i
    float dx = __fadd_rn(__fadd_rn(__fmul_rn(R[0], vx), __fmul_rn(R[3], vy)), R[6]);
    float dy = __fadd_rn(__fadd_rn(__fmul_rn(R[1], vx), __fmul_rn(R[4], vy)), R[7]);
    float dz = __fadd_rn(__fadd_rn(__fmul_rn(R[2], vx), __fmul_rn(R[5], vy)), R[8]);

    float n2 = __fadd_rn(__fadd_rn(__fmul_rn(dx, dx), __fmul_rn(dy, dy)),
                         __fmul_rn(dz, dz));
    float nr = __fsqrt_rn(n2);
    dx = __fdiv_rn(dx, nr);
    dy = __fdiv_rn(dy, nr);
    dz = __fdiv_rn(dz, nr);

    float cx = campos[b * 3 + 0];
    float cy = campos[b * 3 + 1];
    float cz = campos[b * 3 + 2];

    // ---- ray-AABB intersection with [-1,1]^3 (exact divides; inf on /0) ----
    float t1x = __fdiv_rn(__fsub_rn(-1.0f, cx), dx);
    float t2x = __fdiv_rn(__fsub_rn( 1.0f, cx), dx);
    float t1y = __fdiv_rn(__fsub_rn(-1.0f, cy), dy);
    float t2y = __fdiv_rn(__fsub_rn( 1.0f, cy), dy);
    float t1z = __fdiv_rn(__fsub_rn(-1.0f, cz), dz);
    float t2z = __fdiv_rn(__fsub_rn( 1.0f, cz), dz);
    float tmin = fmaxf(fminf(t1x, t2x), fmaxf(fminf(t1y, t2y), fminf(t1z, t2z)));
    float tmax = fminf(fmaxf(t1x, t2x), fminf(fmaxf(t1y, t2y), fmaxf(t1z, t2z)));

    float r = 0.0f, g = 0.0f, bl = 0.0f, alpha = 0.0f;
    size_t obase = ((size_t)b * 4) * HH * WW + (size_t)y * WW + x;

    bool hit = tmin < tmax;
    if (hit && tmax > 0.0f) {
        float t0 = fmaxf(tmin, 0.0f);
        float px = __fadd_rn(cx, __fmul_rn(dx, t0));
        float py = __fadd_rn(cy, __fmul_rn(dy, t0));
        float pz = __fadd_rn(cz, __fmul_rn(dz, t0));
        // DT = 2^-5 exactly -> d*DT exact, step adds bit-identical to reference
        float sx = __fmul_rn(dx, DT);
        float sy = __fmul_rn(dy, DT);
        float sz = __fmul_rn(dz, DT);

        const uint2* __restrict__ vb =
            reinterpret_cast<const uint2*>(g_vol) + (size_t)b * DDD + p * (DV * DV);

        // packed (px,py) state + packed constants
        unsigned long long pxy = packf2(px, py);
        unsigned long long sxy = packf2(sx, sy);
        const unsigned long long C635 = packf2(63.5f, 63.5f);
        // per-lane z-weight as one fma: wz = fz*zs + zo
        const float zs = (p == 0) ? -1.0f : 1.0f;
        const float zo = (p == 0) ?  1.0f : 0.0f;

        bool valid = (fabsf(px) < 1.0f) & (fabsf(py) < 1.0f) & (fabsf(pz) < 1.0f);
        int left = NSTEPS;
        if (!valid) {
            // entry-face rounding: at most ONE leading invalid step; if the
            // next is also invalid the in-box span is < DT and nothing samples
            asm("add.rn.f32x2 %0, %1, %2;" : "=l"(pxy) : "l"(pxy), "l"(sxy));
            pz = __fadd_rn(pz, sz);
            unpackf2(pxy, px, py);
            valid = (fabsf(px) < 1.0f) & (fabsf(py) < 1.0f) & (fabsf(pz) < 1.0f);
            left = valid ? NSTEPS - 1 : 0;
        }

        #pragma unroll 1
        while (left-- > 0) {
            // coords: packed fma for (gx,gy); valid => g in [0,127], no clamp
            unsigned long long gxy;
            asm("fma.rn.f32x2 %0, %1, %2, %2;" : "=l"(gxy) : "l"(pxy), "l"(C635));
            float gx, gy;
            unpackf2(gxy, gx, gy);
            float gz = __fmaf_rn(pz, 63.5f, 63.5f);
            int ix = min((int)gx, DV - 2);
            int iy = min((int)gy, DV - 2);
            int iz = min((int)gz, DV - 2);
            float fx = gx - (float)ix;
            float fy = gy - (float)iy;
            float fz = gz - (float)iz;

            // this lane loads the 4 corners of its z-plane (iz + p)
            int idx = (iz * DV + iy) * DV + ix;
            uint2 r00 = __ldg(vb + idx);
            uint2 r01 = __ldg(vb + idx + 1);
            uint2 r10 = __ldg(vb + idx + DV);
            uint2 r11 = __ldg(vb + idx + DV + 1);

            // advance position early (independent of sample math)
            asm("add.rn.f32x2 %0, %1, %2;" : "=l"(pxy) : "l"(pxy), "l"(sxy));
            pz = __fadd_rn(pz, sz);

            __half2 c00a = *reinterpret_cast<__half2*>(&r00.x);
            __half2 c00b = *reinterpret_cast<__half2*>(&r00.y);
            __half2 c01a = *reinterpret_cast<__half2*>(&r01.x);
            __half2 c01b = *reinterpret_cast<__half2*>(&r01.y);
            __half2 c10a = *reinterpret_cast<__half2*>(&r10.x);
            __half2 c10b = *reinterpret_cast<__half2*>(&r10.y);
            __half2 c11a = *reinterpret_cast<__half2*>(&r11.x);
            __half2 c11b = *reinterpret_cast<__half2*>(&r11.y);

            // fp32 corner weights, pre-multiplied by this lane's z-weight
            float ofx = 1.0f - fx;
            float ofy = 1.0f - fy;
            float wz  = __fmaf_rn(fz, zs, zo);
            float wy0 = ofy * wz;
            float wy1 = fy  * wz;
            __half2 w00 = __float2half2_rn(ofx * wy0);
            __half2 w01 = __float2half2_rn(fx  * wy0);
            __half2 w10 = __float2half2_rn(ofx * wy1);
            __half2 w11 = __float2half2_rn(fx  * wy1);

            // weighted 4-corner sum per packed word (bilinear * z-weight)
            __half2 cpa = __hfma2(c11a, w11,
                          __hfma2(c10a, w10,
                          __hfma2(c01a, w01, __hmul2(c00a, w00))));
            __half2 cpb = __hfma2(c11b, w11,
                          __hfma2(c10b, w10,
                          __hfma2(c01b, w01, __hmul2(c00b, w00))));

            // exchange with sibling lane: 2 packed shuffles
            unsigned m = __activemask();
            unsigned cpa_u = *reinterpret_cast<unsigned*>(&cpa);
            unsigned cpb_u = *reinterpret_cast<unsigned*>(&cpb);
            unsigned cqa_u = __shfl_xor_sync(m, cpa_u, 1);
            unsigned cqb_u = __shfl_xor_sync(m, cpb_u, 1);
            __half2 cqa = *reinterpret_cast<__half2*>(&cqa_u);
            __half2 cqb = *reinterpret_cast<__half2*>(&cqb_u);

            // single commutative add of the identical {cp,cq} pair on both
            // lanes -> smp (and alpha) bit-identical across the pair
            __half2 smpa = __hadd2(cpa, cqa);   // (r,g)
            __half2 smpb = __hadd2(cpb, cqb);   // (b,sigma)

            float2 rg = __half22float2(smpa);
            float2 ba = __half22float2(smpb);

            // sigma*DT exact (11-bit mantissa * 2^-5) -> FFMA == FMUL+FADD bitwise
            float contrib = __fsub_rn(fminf(__fmaf_rn(ba.y, DT, alpha), 1.0f), alpha);
            r  = __fmaf_rn(rg.x, contrib, r);   // rgb: continuous path, fma ok
            g  = __fmaf_rn(rg.y, contrib, g);
            bl = __fmaf_rn(ba.x, contrib, bl);
            alpha = __fadd_rn(alpha, contrib);
            if (alpha >= 1.0f) break;           // contrib exactly 0 afterwards

            unpackf2(pxy, px, py);
            if (!((fabsf(px) < 1.0f) & (fabsf(py) < 1.0f) & (fabsf(pz) < 1.0f)))
                break;                          // convex box: left for good
        }
    }

    if (p == 0) {
        out[obase]               = r;
        out[obase + HH * WW]     = g;
        out[obase + 2 * HH * WW] = bl;
        out[obase + 3 * HH * WW] = alpha;
    }
}

extern "C" void kernel_launch(void* const* d_in, const int* in_sizes, int n_in,
                              void* d_out, int out_size) {
    const float* camrot      = (const float*)d_in[0];
    const float* campos      = (const float*)d_in[1];
    const float* focal       = (const float*)d_in[2];
    const float* princpt     = (const float*)d_in[3];
    const float* pixelcoords = (const float*)d_in[4];
    const float* volume      = (const float*)d_in[5];
    float* out = (float*)d_out;

    int nquads = BB * DDD / 4;
    permute_kernel<<<(nquads + 255) / 256, 256>>>((const float4*)volume);

    dim3 block(64, 4, 1);                 // 256 threads = 128 rays (2 threads/ray)
    dim3 grid(WW / 32, HH / 4, BB);       // 8 x 64 x 2 = 1024 blocks
    raymarch_kernel<<<grid, block>>>(camrot, campos, focal, princpt,
                                     pixelcoords, out);
}